// round 15
// baseline (speedup 1.0000x reference)
#include <cuda_runtime.h>
#include <cuda_bf16.h>
#include <cstdint>

// Problem constants
#define Uu 8192
#define Ii 4096
#define Kk 256
#define NNZ 409600
#define INV_COEFF (1.0f / 5792.6187514801984f)   // 1/sqrt(U*I)

// ===================== device scratch ======================================
static __device__ __align__(16) __nv_bfloat16 g_adjH[(size_t)Uu * Ii];
static __device__ __align__(16) __nv_bfloat16 g_adjL[(size_t)Uu * Ii];
static __device__ __align__(16) __nv_bfloat16 g_nrmH[(size_t)Uu * Ii];
static __device__ __align__(16) __nv_bfloat16 g_nrmL[(size_t)Uu * Ii];
static __device__ __align__(16) __nv_bfloat16 g_CfTH[Kk * Ii], g_CfTL[Kk * Ii];
static __device__ __align__(16) __nv_bfloat16 g_GiTH[Kk * Ii], g_GiTL[Kk * Ii];
static __device__ __align__(16) __nv_bfloat16 g_usfH[Ii * Kk], g_usfL[Ii * Kk];
static __device__ __align__(16) __nv_bfloat16 g_StH[Ii * Kk],  g_StL[Ii * Kk];
static __device__ __align__(16) __nv_bfloat16 g_E1H[Uu * Kk],  g_E1L[Uu * Kk];
static __device__ __align__(16) __nv_bfloat16 g_E2H[Uu * Kk],  g_E2L[Uu * Kk];
static __device__ __align__(16) float g_E1[Uu * Kk];
static __device__ __align__(16) float g_E2[Uu * Kk];
static __device__ __align__(16) float g_Gu[Uu * Kk];
static __device__ unsigned g_colmin[Ii];
static __device__ float    g_colsum[Ii];
static __device__ int      g_minkey[Uu];
static __device__ int      g_rowstart[Uu];
static __device__ int      g_rowcnt[Uu];
static __device__ int      g_colcnt[Ii];
static __device__ int      g_coloff[Ii];
static __device__ int      g_colcur[Ii];
static __device__ int      g_colperm[NNZ];
static __device__ float    g_p1[Uu], g_p2[Uu];
static __device__ int      g_c1[Uu], g_c2[Uu];
static __device__ int      g_has[Uu];

__device__ __forceinline__ unsigned fenc(float f) {
    unsigned u = __float_as_uint(f);
    return (u & 0x80000000u) ? ~u : (u | 0x80000000u);
}
__device__ __forceinline__ float fdec(unsigned e) {
    return (e & 0x80000000u) ? __uint_as_float(e ^ 0x80000000u) : __uint_as_float(~e);
}

// ---------------------------------------------------------------- init
__global__ void init_kernel() {
    int i = blockIdx.x * blockDim.x + threadIdx.x;
    if (i < Ii) { g_colmin[i] = 0xFFFFFFFFu; g_colsum[i] = 0.0f; g_colcnt[i] = 0; }
    if (i < Uu) { g_minkey[i] = 0x7FFFFFFF; g_rowcnt[i] = 0; g_rowstart[i] = 0; }
}

// ------------------------------------------------- build row/col metadata
__global__ void build_kernel(const int* __restrict__ pos_rows,
                             const int* __restrict__ pos_cols) {
    int i = blockIdx.x * blockDim.x + threadIdx.x;
    if (i >= NNZ) return;
    int r = pos_rows[i], c = pos_cols[i];
    atomicAdd(&g_rowcnt[r], 1);
    atomicAdd(&g_colcnt[c], 1);
    if (i == 0 || pos_rows[i - 1] != r) g_rowstart[r] = i;
    atomicMin(&g_minkey[r], c * NNZ + i);
}

// --------------------------------- exclusive scan of column counts (1 block)
__global__ void col_scan_kernel() {
    __shared__ int partial[256];
    int t = threadIdx.x;
    int local[16];
    int s = 0;
#pragma unroll
    for (int j = 0; j < 16; j++) { local[j] = s; s += g_colcnt[t * 16 + j]; }
    partial[t] = s;
    __syncthreads();
    if (t == 0) {
        int run = 0;
        for (int i = 0; i < 256; i++) { int v = partial[i]; partial[i] = run; run += v; }
    }
    __syncthreads();
    int base = partial[t];
#pragma unroll
    for (int j = 0; j < 16; j++) {
        int off = base + local[j];
        g_coloff[t * 16 + j] = off;
        g_colcur[t * 16 + j] = off;
    }
}

// ----------------------------------------- scatter indices sorted by column
__global__ void scatter_kernel(const int* __restrict__ pos_cols) {
    int i = blockIdx.x * blockDim.x + threadIdx.x;
    if (i >= NNZ) return;
    int c = pos_cols[i];
    int p = atomicAdd(&g_colcur[c], 1);
    g_colperm[p] = i;
}

// --------------------------- fp32 -> bf16 hi/lo plane split (vectorized)
__global__ void split_kernel(const float4* __restrict__ src,
                             __nv_bfloat162* __restrict__ hi,
                             __nv_bfloat162* __restrict__ lo, int n4) {
    int i = blockIdx.x * blockDim.x + threadIdx.x;
    if (i >= n4) return;
    float4 v = src[i];
    __nv_bfloat16 hx = __float2bfloat16_rn(v.x);
    __nv_bfloat16 hy = __float2bfloat16_rn(v.y);
    __nv_bfloat16 hz = __float2bfloat16_rn(v.z);
    __nv_bfloat16 hw = __float2bfloat16_rn(v.w);
    hi[2 * i]     = __halves2bfloat162(hx, hy);
    hi[2 * i + 1] = __halves2bfloat162(hz, hw);
    lo[2 * i]     = __halves2bfloat162(__float2bfloat16_rn(v.x - __bfloat162float(hx)),
                                       __float2bfloat16_rn(v.y - __bfloat162float(hy)));
    lo[2 * i + 1] = __halves2bfloat162(__float2bfloat16_rn(v.z - __bfloat162float(hz)),
                                       __float2bfloat16_rn(v.w - __bfloat162float(hw)));
}

// -------- CfT[n,c] = item_sv_f[c,n]/lam_pos[n] -> bf16 hi/lo [256,4096]
__global__ void cft_kernel(const float* __restrict__ isf,
                           const float* __restrict__ lamp) {
    __shared__ float t[32][33];
    int c_in = blockIdx.x * 32 + threadIdx.y;
    int k_in = blockIdx.y * 32 + threadIdx.x;
    t[threadIdx.y][threadIdx.x] = isf[c_in * Kk + k_in] / lamp[k_in];
    __syncthreads();
    int c_out = blockIdx.x * 32 + threadIdx.x;
    int k_out = blockIdx.y * 32 + threadIdx.y;
    float x = t[threadIdx.x][threadIdx.y];
    __nv_bfloat16 h = __float2bfloat16_rn(x);
    g_CfTH[k_out * Ii + c_out] = h;
    g_CfTL[k_out * Ii + c_out] = __float2bfloat16_rn(x - __bfloat162float(h));
}

// ---------------- user GNN: G_u.  4 rows/block, 64 threads/row, float4/k.
__global__ void __launch_bounds__(256) user_gnn_kernel(
    const int* __restrict__ pos_cols, const float* __restrict__ pos_vals,
    const float* __restrict__ item_sv, const float* __restrict__ user_sv) {
    int tid = threadIdx.x;
    int seg = tid >> 6, lane = tid & 63;
    int r = blockIdx.x * 4 + seg;
    int s0 = g_rowstart[r], n = g_rowcnt[r];
    const float4* isv = (const float4*)item_sv;
    float4 acc = make_float4(0.f, 0.f, 0.f, 0.f);
    int j = 0;
    for (; j + 4 <= n; j += 4) {
        int c0 = __ldg(&pos_cols[s0 + j]);
        int c1 = __ldg(&pos_cols[s0 + j + 1]);
        int c2 = __ldg(&pos_cols[s0 + j + 2]);
        int c3 = __ldg(&pos_cols[s0 + j + 3]);
        float v0 = __ldg(&pos_vals[s0 + j]);
        float v1 = __ldg(&pos_vals[s0 + j + 1]);
        float v2 = __ldg(&pos_vals[s0 + j + 2]);
        float v3 = __ldg(&pos_vals[s0 + j + 3]);
        float4 a0 = isv[c0 * 64 + lane];
        float4 a1 = isv[c1 * 64 + lane];
        float4 a2 = isv[c2 * 64 + lane];
        float4 a3 = isv[c3 * 64 + lane];
        acc.x += v0 * a0.x + v1 * a1.x + v2 * a2.x + v3 * a3.x;
        acc.y += v0 * a0.y + v1 * a1.y + v2 * a2.y + v3 * a3.y;
        acc.z += v0 * a0.z + v1 * a1.z + v2 * a2.z + v3 * a3.z;
        acc.w += v0 * a0.w + v1 * a1.w + v2 * a2.w + v3 * a3.w;
    }
    for (; j < n; j++) {
        int c = __ldg(&pos_cols[s0 + j]);
        float v = __ldg(&pos_vals[s0 + j]);
        float4 a = isv[c * 64 + lane];
        acc.x += v * a.x; acc.y += v * a.y; acc.z += v * a.z; acc.w += v * a.w;
    }
    float4 us = ((const float4*)user_sv)[r * 64 + lane];
    float4 o;
    o.x = 0.5f * (acc.x * INV_COEFF + us.x);
    o.y = 0.5f * (acc.y * INV_COEFF + us.y);
    o.z = 0.5f * (acc.z * INV_COEFF + us.z);
    o.w = 0.5f * (acc.w * INV_COEFF + us.w);
    ((float4*)g_Gu)[r * 64 + lane] = o;
}

// -------- fused item GNN (/lambda folded, -> GiT hi/lo) + St hi/lo.
__global__ void __launch_bounds__(256) item_s_kernel(
    const int* __restrict__ pos_rows, const float* __restrict__ pos_vals,
    const float* __restrict__ user_sv, const float* __restrict__ item_sv,
    const float* __restrict__ lambda_mat) {
    int tid = threadIdx.x;
    int seg = tid >> 6, lane = tid & 63;
    int c = blockIdx.x * 4 + seg;
    int s0 = g_coloff[c], n = g_colcnt[c];
    const float4* usv = (const float4*)user_sv;
    const float4* guv = (const float4*)g_Gu;
    float4 accI = make_float4(0.f, 0.f, 0.f, 0.f);
    float4 accS = make_float4(0.f, 0.f, 0.f, 0.f);
    int j = 0;
    for (; j + 4 <= n; j += 4) {
        int p0 = __ldg(&g_colperm[s0 + j]);
        int p1 = __ldg(&g_colperm[s0 + j + 1]);
        int p2 = __ldg(&g_colperm[s0 + j + 2]);
        int p3 = __ldg(&g_colperm[s0 + j + 3]);
        int r0 = __ldg(&pos_rows[p0]);
        int r1 = __ldg(&pos_rows[p1]);
        int r2 = __ldg(&pos_rows[p2]);
        int r3 = __ldg(&pos_rows[p3]);
        float v0 = __ldg(&pos_vals[p0]);
        float v1 = __ldg(&pos_vals[p1]);
        float v2 = __ldg(&pos_vals[p2]);
        float v3 = __ldg(&pos_vals[p3]);
        float4 u0 = usv[r0 * 64 + lane];
        float4 u1 = usv[r1 * 64 + lane];
        float4 u2 = usv[r2 * 64 + lane];
        float4 u3 = usv[r3 * 64 + lane];
        float4 q0 = guv[r0 * 64 + lane];
        float4 q1 = guv[r1 * 64 + lane];
        float4 q2 = guv[r2 * 64 + lane];
        float4 q3 = guv[r3 * 64 + lane];
        accI.x += v0 * u0.x + v1 * u1.x + v2 * u2.x + v3 * u3.x;
        accI.y += v0 * u0.y + v1 * u1.y + v2 * u2.y + v3 * u3.y;
        accI.z += v0 * u0.z + v1 * u1.z + v2 * u2.z + v3 * u3.z;
        accI.w += v0 * u0.w + v1 * u1.w + v2 * u2.w + v3 * u3.w;
        accS.x += v0 * q0.x + v1 * q1.x + v2 * q2.x + v3 * q3.x;
        accS.y += v0 * q0.y + v1 * q1.y + v2 * q2.y + v3 * q3.y;
        accS.z += v0 * q0.z + v1 * q1.z + v2 * q2.z + v3 * q3.z;
        accS.w += v0 * q0.w + v1 * q1.w + v2 * q2.w + v3 * q3.w;
    }
    for (; j < n; j++) {
        int p = __ldg(&g_colperm[s0 + j]);
        int r = __ldg(&pos_rows[p]);
        float v = __ldg(&pos_vals[p]);
        float4 u = usv[r * 64 + lane];
        float4 q = guv[r * 64 + lane];
        accI.x += v * u.x; accI.y += v * u.y; accI.z += v * u.z; accI.w += v * u.w;
        accS.x += v * q.x; accS.y += v * q.y; accS.z += v * q.z; accS.w += v * q.w;
    }
    float4 iv = ((const float4*)item_sv)[c * 64 + lane];
    float4 lam = ((const float4*)lambda_mat)[lane];
    float gi[4], st[4];
    gi[0] = 0.5f * (accI.x * INV_COEFF + iv.x) / lam.x;
    gi[1] = 0.5f * (accI.y * INV_COEFF + iv.y) / lam.y;
    gi[2] = 0.5f * (accI.z * INV_COEFF + iv.z) / lam.z;
    gi[3] = 0.5f * (accI.w * INV_COEFF + iv.w) / lam.w;
    st[0] = accS.x; st[1] = accS.y; st[2] = accS.z; st[3] = accS.w;
#pragma unroll
    for (int i = 0; i < 4; i++) {
        int k = lane * 4 + i;
        __nv_bfloat16 h = __float2bfloat16_rn(gi[i]);
        g_GiTH[k * Ii + c] = h;
        g_GiTL[k * Ii + c] = __float2bfloat16_rn(gi[i] - __bfloat162float(h));
        __nv_bfloat16 sh = __float2bfloat16_rn(st[i]);
        g_StH[c * Kk + k] = sh;
        g_StL[c * Kk + k] = __float2bfloat16_rn(st[i] - __bfloat162float(sh));
    }
}

// ===================== mma.sync bf16-split GEMM ============================
// CTA tile 128x64, 256 threads (8 warps, 2x4, warp tile 64x16), BK=64,
// 2-stage cp.async double buffer, 2 CTAs per SM (phase-desynchronized so one
// CTA's MMA bursts cover the other's LDS/barrier phases).

__device__ __forceinline__ void cp16(uint32_t dst, const void* src) {
    asm volatile("cp.async.cg.shared.global [%0], [%1], 16;"
                 :: "r"(dst), "l"(__cvta_generic_to_global(src)));
}
#define CP_COMMIT() asm volatile("cp.async.commit_group;")
#define CP_WAIT1()  asm volatile("cp.async.wait_group 1;")

__device__ __forceinline__ uint32_t smem_u32(const void* p) {
    uint32_t a;
    asm("{ .reg .u64 t; cvta.to.shared.u64 t, %1; cvt.u32.u64 %0, t; }"
        : "=r"(a) : "l"(p));
    return a;
}

#define MMA_BF16(d, a, b) \
    asm volatile("mma.sync.aligned.m16n8k16.row.col.f32.bf16.bf16.f32 " \
        "{%0,%1,%2,%3}, {%4,%5,%6,%7}, {%8,%9}, {%0,%1,%2,%3};" \
        : "+f"((d)[0]), "+f"((d)[1]), "+f"((d)[2]), "+f"((d)[3]) \
        : "r"((a)[0]), "r"((a)[1]), "r"((a)[2]), "r"((a)[3]), \
          "r"((b)[0]), "r"((b)[1]))

#define A_PLANE 16384          // 128 rows x 128 B
#define B_PLANE 8192           // 64 rows x 128 B
#define STAGE   49152          // Ahi,Alo,Bhi,Blo
#define B_OFF   32768
#define GEMM_SMEM 98304        // 2 stages
#define GEMM_THREADS 256

template <int MODE>
__device__ __forceinline__ void gemm_core(
    int M, int N, int K,
    const __nv_bfloat16* __restrict__ AH, const __nv_bfloat16* __restrict__ AL,
    const __nv_bfloat16* __restrict__ BH, const __nv_bfloat16* __restrict__ BL,
    float* __restrict__ C,
    __nv_bfloat16* __restrict__ CH, __nv_bfloat16* __restrict__ CL,
    unsigned* cmin, float* csum, char* dsm)
{
    __shared__ unsigned sMin[64];
    __shared__ float sSum[64];

    int tid = threadIdx.x;
    int l = tid & 31, wid = tid >> 5;            // 8 warps
    int wm = wid >> 2, wn = wid & 3;             // 2 x 4, warp tile 64x16
    int m0 = blockIdx.y * 128, n0 = blockIdx.x * 64;

    if (MODE == 1 && tid < 64) { sMin[tid] = 0xFFFFFFFFu; sSum[tid] = 0.0f; }

    float acc[4][2][4];
#pragma unroll
    for (int a = 0; a < 4; a++)
#pragma unroll
        for (int b = 0; b < 2; b++)
#pragma unroll
            for (int c = 0; c < 4; c++) acc[a][b][c] = 0.0f;

    uint32_t sb = smem_u32(dsm);
    int ar = tid >> 1, ac = (tid & 1) * 4;   // A: 128 rows, 4 chunks/thread/plane
    int br = tid >> 2, bc = (tid & 3) * 2;   // B: 64 rows, 2 chunks/thread/plane
    int afw = ar & 7, bfw = br & 7;

    int NIT = K >> 6;

    auto load_stage = [&](int s, int it) {
        uint32_t stb = sb + s * STAGE;
        int k0 = it << 6;
        const __nv_bfloat16* ah = AH + (size_t)(m0 + ar) * K + k0;
        const __nv_bfloat16* al = AL + (size_t)(m0 + ar) * K + k0;
        const __nv_bfloat16* bh = BH + (size_t)(n0 + br) * K + k0;
        const __nv_bfloat16* bl = BL + (size_t)(n0 + br) * K + k0;
#pragma unroll
        for (int c = ac; c < ac + 4; c++) {
            uint32_t off = ar * 128 + ((c ^ afw) & 7) * 16;
            cp16(stb + off,           ah + c * 8);
            cp16(stb + A_PLANE + off, al + c * 8);
        }
#pragma unroll
        for (int c = bc; c < bc + 2; c++) {
            uint32_t off = br * 128 + ((c ^ bfw) & 7) * 16;
            cp16(stb + B_OFF + off,           bh + c * 8);
            cp16(stb + B_OFF + B_PLANE + off, bl + c * 8);
        }
    };

    load_stage(0, 0);
    CP_COMMIT();

    for (int it = 0; it < NIT; it++) {
        if (it + 1 < NIT) load_stage((it + 1) & 1, it + 1);
        CP_COMMIT();
        CP_WAIT1();
        __syncthreads();

        const char* st = dsm + (it & 1) * STAGE;
#pragma unroll
        for (int ks = 0; ks < 4; ks++) {
            uint32_t ah[4][4], al4[4][4], bh[2][2], bl4[2][2];
#pragma unroll
            for (int mt = 0; mt < 4; mt++) {
                int row = wm * 64 + mt * 16 + (l >> 2);
                int f = row & 7;             // same for row and row+8
                int pos = (l & 3) << 2;
                uint32_t o00 = row * 128 + (((ks * 2)     ^ f) << 4) + pos;
                uint32_t o01 = row * 128 + (((ks * 2 + 1) ^ f) << 4) + pos;
                uint32_t o10 = (row + 8) * 128 + (((ks * 2)     ^ f) << 4) + pos;
                uint32_t o11 = (row + 8) * 128 + (((ks * 2 + 1) ^ f) << 4) + pos;
                ah[mt][0] = *(const uint32_t*)(st + o00);
                ah[mt][1] = *(const uint32_t*)(st + o10);
                ah[mt][2] = *(const uint32_t*)(st + o01);
                ah[mt][3] = *(const uint32_t*)(st + o11);
                al4[mt][0] = *(const uint32_t*)(st + A_PLANE + o00);
                al4[mt][1] = *(const uint32_t*)(st + A_PLANE + o10);
                al4[mt][2] = *(const uint32_t*)(st + A_PLANE + o01);
                al4[mt][3] = *(const uint32_t*)(st + A_PLANE + o11);
            }
#pragma unroll
            for (int nt = 0; nt < 2; nt++) {
                int row = wn * 16 + nt * 8 + (l >> 2);
                int f = row & 7;
                int pos = (l & 3) << 2;
                uint32_t o0 = row * 128 + (((ks * 2)     ^ f) << 4) + pos;
                uint32_t o1 = row * 128 + (((ks * 2 + 1) ^ f) << 4) + pos;
                bh[nt][0] = *(const uint32_t*)(st + B_OFF + o0);
                bh[nt][1] = *(const uint32_t*)(st + B_OFF + o1);
                bl4[nt][0] = *(const uint32_t*)(st + B_OFF + B_PLANE + o0);
                bl4[nt][1] = *(const uint32_t*)(st + B_OFF + B_PLANE + o1);
            }
#pragma unroll
            for (int mt = 0; mt < 4; mt++)
#pragma unroll
                for (int nt = 0; nt < 2; nt++) {
                    MMA_BF16(acc[mt][nt], ah[mt], bh[nt]);
                    MMA_BF16(acc[mt][nt], ah[mt], bl4[nt]);
                    MMA_BF16(acc[mt][nt], al4[mt], bh[nt]);
                }
        }
        __syncthreads();   // 2-stage buffer: readers done before overwrite
    }

    if (MODE == 0 || MODE == 2) {
#pragma unroll
        for (int mt = 0; mt < 4; mt++) {
            int row = m0 + wm * 64 + mt * 16 + (l >> 2);
#pragma unroll
            for (int nt = 0; nt < 2; nt++) {
                int col = n0 + wn * 16 + nt * 8 + ((l & 3) << 1);
                float v0 = acc[mt][nt][0], v1 = acc[mt][nt][1];
                float v2 = acc[mt][nt][2], v3 = acc[mt][nt][3];
                *(float2*)&C[(size_t)row * N + col] = make_float2(v0, v1);
                *(float2*)&C[(size_t)(row + 8) * N + col] = make_float2(v2, v3);
                if (MODE == 2) {
                    __nv_bfloat16 h0 = __float2bfloat16_rn(v0);
                    __nv_bfloat16 h1 = __float2bfloat16_rn(v1);
                    __nv_bfloat16 h2 = __float2bfloat16_rn(v2);
                    __nv_bfloat16 h3 = __float2bfloat16_rn(v3);
                    *(__nv_bfloat162*)&CH[(size_t)row * N + col] = __halves2bfloat162(h0, h1);
                    *(__nv_bfloat162*)&CH[(size_t)(row + 8) * N + col] = __halves2bfloat162(h2, h3);
                    *(__nv_bfloat162*)&CL[(size_t)row * N + col] =
                        __halves2bfloat162(__float2bfloat16_rn(v0 - __bfloat162float(h0)),
                                           __float2bfloat16_rn(v1 - __bfloat162float(h1)));
                    *(__nv_bfloat162*)&CL[(size_t)(row + 8) * N + col] =
                        __halves2bfloat162(__float2bfloat16_rn(v2 - __bfloat162float(h2)),
                                           __float2bfloat16_rn(v3 - __bfloat162float(h3)));
                }
            }
        }
    } else {   // MODE 1: fused column min/sum (64 columns per CTA)
#pragma unroll
        for (int nt = 0; nt < 2; nt++) {
            float mn0 = acc[0][nt][0], sm0 = 0.0f;
            float mn1 = acc[0][nt][1], sm1 = 0.0f;
#pragma unroll
            for (int mt = 0; mt < 4; mt++) {
                mn0 = fminf(mn0, fminf(acc[mt][nt][0], acc[mt][nt][2]));
                sm0 += acc[mt][nt][0] + acc[mt][nt][2];
                mn1 = fminf(mn1, fminf(acc[mt][nt][1], acc[mt][nt][3]));
                sm1 += acc[mt][nt][1] + acc[mt][nt][3];
            }
#pragma unroll
            for (int d = 4; d < 32; d <<= 1) {
                sm0 += __shfl_xor_sync(0xFFFFFFFFu, sm0, d);
                sm1 += __shfl_xor_sync(0xFFFFFFFFu, sm1, d);
                mn0 = fminf(mn0, __shfl_xor_sync(0xFFFFFFFFu, mn0, d));
                mn1 = fminf(mn1, __shfl_xor_sync(0xFFFFFFFFu, mn1, d));
            }
            if ((l >> 2) == 0) {
                int c = wn * 16 + nt * 8 + ((l & 3) << 1);
                atomicMin(&sMin[c], fenc(mn0));
                atomicAdd(&sSum[c], sm0);
                atomicMin(&sMin[c + 1], fenc(mn1));
                atomicAdd(&sSum[c + 1], sm1);
            }
        }
        __syncthreads();
        if (tid < 64) {
            atomicMin(&cmin[n0 + tid], sMin[tid]);
            atomicAdd(&csum[n0 + tid], sSum[tid]);
        }
    }
}

// wrappers
__global__ void __launch_bounds__(GEMM_THREADS, 2) gemm_e_kernel(
    const __nv_bfloat16* AH, const __nv_bfloat16* AL,
    const __nv_bfloat16* BH, const __nv_bfloat16* BL,
    float* C, __nv_bfloat16* CH, __nv_bfloat16* CL) {
    extern __shared__ char dsm[];
    gemm_core<2>(Uu, Kk, Ii, AH, AL, BH, BL, C, CH, CL, nullptr, nullptr, dsm);
}

__global__ void __launch_bounds__(GEMM_THREADS, 2) gemm_stats_kernel(
    const __nv_bfloat16* AH, const __nv_bfloat16* AL,
    const __nv_bfloat16* BH, const __nv_bfloat16* BL,
    unsigned* cmin, float* csum) {
    extern __shared__ char dsm[];
    gemm_core<1>(Uu, Ii, Kk, AH, AL, BH, BL,
                 nullptr, nullptr, nullptr, cmin, csum, dsm);
}

__global__ void __launch_bounds__(GEMM_THREADS, 2) gemm_out_kernel(
    const __nv_bfloat16* AH, const __nv_bfloat16* AL,
    const __nv_bfloat16* BH, const __nv_bfloat16* BL,
    float* C) {
    extern __shared__ char dsm[];
    gemm_core<0>(Uu, Ii, Kk, AH, AL, BH, BL,
                 C, nullptr, nullptr, nullptr, nullptr, dsm);
}

// ------------------- per-row mat_expo entries -> p1/p2 (compute_P fusion)
__global__ void entry_kernel(const int* __restrict__ pos_cols,
                             const float* __restrict__ pos_vals,
                             const float* __restrict__ usf) {
    int r = blockIdx.x, t = threadIdx.x;
    int mk = g_minkey[r];
    if (mk == 0x7FFFFFFF) { if (t == 0) g_has[r] = 0; return; }
    int eidx = mk % NNZ;
    int c1 = pos_cols[eidx];
    float v1 = pos_vals[eidx];
    int c2 = (c1 + 1) & (Ii - 1);
    float a = g_E1[r * Kk + t];
    float e1 = a * usf[c1 * Kk + t];
    float e2 = a * usf[c2 * Kk + t];
    __shared__ float s1[256], s2[256];
    s1[t] = e1; s2[t] = e2;
    __syncthreads();
    for (int off = 128; off > 0; off >>= 1) {
        if (t < off) { s1[t] += s1[t + off]; s2[t] += s2[t + off]; }
        __syncthreads();
    }
    if (t == 0) {
        float E1v = s1[0], E2v = s2[0];
        float m1 = fdec(g_colmin[c1]), m2 = fdec(g_colmin[c2]);
        float sum1 = g_colsum[c1] - (float)Uu * m1 + (float)Uu * 1e-8f;
        float sum2 = g_colsum[c2] - (float)Uu * m2 + (float)Uu * 1e-8f;
        float n1 = (E1v - m1 + 1e-8f) / sum1;
        float n2 = (E2v - m2 + 1e-8f) / sum2;
        float d1 = (v1 == 0.0f) ? 1e-5f : v1;
        float d2 = (v1 == 0.0f) ? 1e-5f : -v1;
        g_p1[r] = n1 / d1;
        g_p2[r] = n2 / d2;
        g_c1[r] = c1;
        g_c2[r] = c2;
        g_has[r] = 1;
    }
}

// ------------------------------------------- out += 0.2 * mat_adjust
__global__ void adjust_kernel(float* __restrict__ out) {
    int r = blockIdx.x * blockDim.x + threadIdx.x;
    if (r >= Uu || !g_has[r]) return;
    out[(size_t)r * Ii + g_c1[r]] += 0.2f * g_p1[r];
    out[(size_t)r * Ii + g_c2[r]] += 0.2f * g_p2[r];
}

extern "C" void kernel_launch(void* const* d_in, const int* in_sizes, int n_in,
                              void* d_out, int out_size) {
    const float* adj       = (const float*)d_in[0];
    const float* norm_adj  = (const float*)d_in[1];
    const float* user_sv   = (const float*)d_in[2];
    const float* item_sv   = (const float*)d_in[3];
    const float* user_sv_f = (const float*)d_in[4];
    const float* item_sv_f = (const float*)d_in[5];
    const int*   pos_rows  = (const int*)d_in[6];
    const int*   pos_cols  = (const int*)d_in[7];
    const float* pos_vals  = (const float*)d_in[8];
    const float* lambda_m  = (const float*)d_in[9];
    const float* lambda_p  = (const float*)d_in[10];
    float* out = (float*)d_out;

    void *adjH, *adjL, *nrmH, *nrmL, *cfH, *cfL, *giH, *giL;
    void *usH, *usL, *stH, *stL, *e1H, *e1L, *e2H, *e2L, *e1f, *e2f;
    void *cminp, *csump;
    cudaGetSymbolAddress(&adjH, g_adjH); cudaGetSymbolAddress(&adjL, g_adjL);
    cudaGetSymbolAddress(&nrmH, g_nrmH); cudaGetSymbolAddress(&nrmL, g_nrmL);
    cudaGetSymbolAddress(&cfH, g_CfTH);  cudaGetSymbolAddress(&cfL, g_CfTL);
    cudaGetSymbolAddress(&giH, g_GiTH);  cudaGetSymbolAddress(&giL, g_GiTL);
    cudaGetSymbolAddress(&usH, g_usfH);  cudaGetSymbolAddress(&usL, g_usfL);
    cudaGetSymbolAddress(&stH, g_StH);   cudaGetSymbolAddress(&stL, g_StL);
    cudaGetSymbolAddress(&e1H, g_E1H);   cudaGetSymbolAddress(&e1L, g_E1L);
    cudaGetSymbolAddress(&e2H, g_E2H);   cudaGetSymbolAddress(&e2L, g_E2L);
    cudaGetSymbolAddress(&e1f, g_E1);    cudaGetSymbolAddress(&e2f, g_E2);
    cudaGetSymbolAddress(&cminp, g_colmin); cudaGetSymbolAddress(&csump, g_colsum);

    cudaFuncSetAttribute(gemm_e_kernel, cudaFuncAttributeMaxDynamicSharedMemorySize, GEMM_SMEM);
    cudaFuncSetAttribute(gemm_stats_kernel, cudaFuncAttributeMaxDynamicSharedMemorySize, GEMM_SMEM);
    cudaFuncSetAttribute(gemm_out_kernel, cudaFuncAttributeMaxDynamicSharedMemorySize, GEMM_SMEM);

    // one-time stream/event creation (host resources, not device memory)
    static cudaStream_t s2 = nullptr, s3 = nullptr;
    static cudaEvent_t evFork, evBuild, evNrm, evUsf, evEntry;
    if (s2 == nullptr) {
        cudaStreamCreateWithFlags(&s2, cudaStreamNonBlocking);
        cudaStreamCreateWithFlags(&s3, cudaStreamNonBlocking);
        cudaEventCreateWithFlags(&evFork,  cudaEventDisableTiming);
        cudaEventCreateWithFlags(&evBuild, cudaEventDisableTiming);
        cudaEventCreateWithFlags(&evNrm,   cudaEventDisableTiming);
        cudaEventCreateWithFlags(&evUsf,   cudaEventDisableTiming);
        cudaEventCreateWithFlags(&evEntry, cudaEventDisableTiming);
    }

    // ---- main: init, then fork
    init_kernel<<<Uu / 256, 256>>>();
    cudaEventRecord(evFork, 0);
    cudaStreamWaitEvent(s2, evFork, 0);
    cudaStreamWaitEvent(s3, evFork, 0);

    // ---- s2: adj planes -> CfT planes -> GEMM1 (E1 + planes)
    split_kernel<<<(Uu * Ii / 4 + 255) / 256, 256, 0, s2>>>(
        (const float4*)adj, (__nv_bfloat162*)adjH, (__nv_bfloat162*)adjL, Uu * Ii / 4);
    cft_kernel<<<dim3(Ii / 32, Kk / 32), dim3(32, 32), 0, s2>>>(item_sv_f, lambda_p);
    gemm_e_kernel<<<dim3(Kk / 64, Uu / 128), GEMM_THREADS, GEMM_SMEM, s2>>>(
        (const __nv_bfloat16*)adjH, (const __nv_bfloat16*)adjL,
        (const __nv_bfloat16*)cfH,  (const __nv_bfloat16*)cfL,
        (float*)e1f, (__nv_bfloat16*)e1H, (__nv_bfloat16*)e1L);

    // ---- s3: norm planes, usf planes
    split_kernel<<<(Uu * Ii / 4 + 255) / 256, 256, 0, s3>>>(
        (const float4*)norm_adj, (__nv_bfloat162*)nrmH, (__nv_bfloat162*)nrmL, Uu * Ii / 4);
    cudaEventRecord(evNrm, s3);
    split_kernel<<<(Ii * Kk / 4 + 255) / 256, 256, 0, s3>>>(
        (const float4*)user_sv_f, (__nv_bfloat162*)usH, (__nv_bfloat162*)usL, Ii * Kk / 4);
    cudaEventRecord(evUsf, s3);

    // ---- main: sparse metadata + GNN chain
    build_kernel<<<(NNZ + 255) / 256, 256>>>(pos_rows, pos_cols);
    cudaEventRecord(evBuild, 0);
    col_scan_kernel<<<1, 256>>>();
    scatter_kernel<<<(NNZ + 255) / 256, 256>>>(pos_cols);
    user_gnn_kernel<<<Uu / 4, 256>>>(pos_cols, pos_vals, item_sv, user_sv);
    item_s_kernel<<<Ii / 4, 256>>>(pos_rows, pos_vals, user_sv, item_sv, lambda_m);

    // ---- s2: stats GEMM (needs E1 planes + usf planes), then entry
    cudaStreamWaitEvent(s2, evUsf, 0);
    gemm_stats_kernel<<<dim3(Ii / 64, Uu / 128), GEMM_THREADS, GEMM_SMEM, s2>>>(
        (const __nv_bfloat16*)e1H, (const __nv_bfloat16*)e1L,
        (const __nv_bfloat16*)usH, (const __nv_bfloat16*)usL,
        (unsigned*)cminp, (float*)csump);
    cudaStreamWaitEvent(s2, evBuild, 0);
    entry_kernel<<<Uu, 256, 0, s2>>>(pos_cols, pos_vals, user_sv_f);
    cudaEventRecord(evEntry, s2);

    // ---- main: GEMM2 (needs nrm planes + GiT from item_s), out GEMM, adjust
    cudaStreamWaitEvent(0, evNrm, 0);
    gemm_e_kernel<<<dim3(Kk / 64, Uu / 128), GEMM_THREADS, GEMM_SMEM>>>(
        (const __nv_bfloat16*)nrmH, (const __nv_bfloat16*)nrmL,
        (const __nv_bfloat16*)giH,  (const __nv_bfloat16*)giL,
        (float*)e2f, (__nv_bfloat16*)e2H, (__nv_bfloat16*)e2L);
    gemm_out_kernel<<<dim3(Ii / 64, Uu / 128), GEMM_THREADS, GEMM_SMEM>>>(
        (const __nv_bfloat16*)e2H, (const __nv_bfloat16*)e2L,
        (const __nv_bfloat16*)stH, (const __nv_bfloat16*)stL, out);
    cudaStreamWaitEvent(0, evEntry, 0);
    adjust_kernel<<<Uu / 256, 256>>>(out);
}

// round 16
// speedup vs baseline: 1.2006x; 1.2006x over previous
#include <cuda_runtime.h>
#include <cuda_bf16.h>
#include <cstdint>

// Problem constants
#define Uu 8192
#define Ii 4096
#define Kk 256
#define NNZ 409600
#define INV_COEFF (1.0f / 5792.6187514801984f)   // 1/sqrt(U*I)

// ===================== device scratch ======================================
static __device__ __align__(16) __nv_bfloat16 g_adjH[(size_t)Uu * Ii];
static __device__ __align__(16) __nv_bfloat16 g_adjL[(size_t)Uu * Ii];
static __device__ __align__(16) __nv_bfloat16 g_nrmH[(size_t)Uu * Ii];
static __device__ __align__(16) __nv_bfloat16 g_nrmL[(size_t)Uu * Ii];
static __device__ __align__(16) __nv_bfloat16 g_CfTH[Kk * Ii], g_CfTL[Kk * Ii];
static __device__ __align__(16) __nv_bfloat16 g_GiTH[Kk * Ii], g_GiTL[Kk * Ii];
static __device__ __align__(16) __nv_bfloat16 g_usfH[Ii * Kk], g_usfL[Ii * Kk];
static __device__ __align__(16) __nv_bfloat16 g_StH[Ii * Kk],  g_StL[Ii * Kk];
static __device__ __align__(16) __nv_bfloat16 g_E1H[Uu * Kk],  g_E1L[Uu * Kk];
static __device__ __align__(16) __nv_bfloat16 g_E2H[Uu * Kk],  g_E2L[Uu * Kk];
static __device__ __align__(16) float g_E1[Uu * Kk];
static __device__ __align__(16) float g_E2[Uu * Kk];
static __device__ __align__(16) float g_Gu[Uu * Kk];
static __device__ unsigned g_colmin[Ii];
static __device__ float    g_colsum[Ii];
static __device__ int      g_minkey[Uu];
static __device__ int      g_rowstart[Uu];
static __device__ int      g_rowcnt[Uu];
static __device__ int      g_colcnt[Ii];
static __device__ int      g_coloff[Ii];
static __device__ int      g_colcur[Ii];
static __device__ int      g_colperm[NNZ];
static __device__ float    g_p1[Uu], g_p2[Uu];
static __device__ int      g_c1[Uu], g_c2[Uu];
static __device__ int      g_has[Uu];

__device__ __forceinline__ unsigned fenc(float f) {
    unsigned u = __float_as_uint(f);
    return (u & 0x80000000u) ? ~u : (u | 0x80000000u);
}
__device__ __forceinline__ float fdec(unsigned e) {
    return (e & 0x80000000u) ? __uint_as_float(e ^ 0x80000000u) : __uint_as_float(~e);
}

// ---------------------------------------------------------------- init
__global__ void init_kernel() {
    int i = blockIdx.x * blockDim.x + threadIdx.x;
    if (i < Ii) { g_colmin[i] = 0xFFFFFFFFu; g_colsum[i] = 0.0f; g_colcnt[i] = 0; }
    if (i < Uu) { g_minkey[i] = 0x7FFFFFFF; g_rowcnt[i] = 0; g_rowstart[i] = 0; }
}

// ------------------------------------------------- build row/col metadata
__global__ void build_kernel(const int* __restrict__ pos_rows,
                             const int* __restrict__ pos_cols) {
    int i = blockIdx.x * blockDim.x + threadIdx.x;
    if (i >= NNZ) return;
    int r = pos_rows[i], c = pos_cols[i];
    atomicAdd(&g_rowcnt[r], 1);
    atomicAdd(&g_colcnt[c], 1);
    if (i == 0 || pos_rows[i - 1] != r) g_rowstart[r] = i;
    atomicMin(&g_minkey[r], c * NNZ + i);
}

// --------------------------------- exclusive scan of column counts (1 block)
__global__ void col_scan_kernel() {
    __shared__ int partial[256];
    int t = threadIdx.x;
    int local[16];
    int s = 0;
#pragma unroll
    for (int j = 0; j < 16; j++) { local[j] = s; s += g_colcnt[t * 16 + j]; }
    partial[t] = s;
    __syncthreads();
    if (t == 0) {
        int run = 0;
        for (int i = 0; i < 256; i++) { int v = partial[i]; partial[i] = run; run += v; }
    }
    __syncthreads();
    int base = partial[t];
#pragma unroll
    for (int j = 0; j < 16; j++) {
        int off = base + local[j];
        g_coloff[t * 16 + j] = off;
        g_colcur[t * 16 + j] = off;
    }
}

// ----------------------------------------- scatter indices sorted by column
__global__ void scatter_kernel(const int* __restrict__ pos_cols) {
    int i = blockIdx.x * blockDim.x + threadIdx.x;
    if (i >= NNZ) return;
    int c = pos_cols[i];
    int p = atomicAdd(&g_colcur[c], 1);
    g_colperm[p] = i;
}

// --------------------------- fp32 -> bf16 hi/lo plane split (vectorized)
__global__ void split_kernel(const float4* __restrict__ src,
                             __nv_bfloat162* __restrict__ hi,
                             __nv_bfloat162* __restrict__ lo, int n4) {
    int i = blockIdx.x * blockDim.x + threadIdx.x;
    if (i >= n4) return;
    float4 v = src[i];
    __nv_bfloat16 hx = __float2bfloat16_rn(v.x);
    __nv_bfloat16 hy = __float2bfloat16_rn(v.y);
    __nv_bfloat16 hz = __float2bfloat16_rn(v.z);
    __nv_bfloat16 hw = __float2bfloat16_rn(v.w);
    hi[2 * i]     = __halves2bfloat162(hx, hy);
    hi[2 * i + 1] = __halves2bfloat162(hz, hw);
    lo[2 * i]     = __halves2bfloat162(__float2bfloat16_rn(v.x - __bfloat162float(hx)),
                                       __float2bfloat16_rn(v.y - __bfloat162float(hy)));
    lo[2 * i + 1] = __halves2bfloat162(__float2bfloat16_rn(v.z - __bfloat162float(hz)),
                                       __float2bfloat16_rn(v.w - __bfloat162float(hw)));
}

// -------- CfT[n,c] = item_sv_f[c,n]/lam_pos[n] -> bf16 hi/lo [256,4096]
__global__ void cft_kernel(const float* __restrict__ isf,
                           const float* __restrict__ lamp) {
    __shared__ float t[32][33];
    int c_in = blockIdx.x * 32 + threadIdx.y;
    int k_in = blockIdx.y * 32 + threadIdx.x;
    t[threadIdx.y][threadIdx.x] = isf[c_in * Kk + k_in] / lamp[k_in];
    __syncthreads();
    int c_out = blockIdx.x * 32 + threadIdx.x;
    int k_out = blockIdx.y * 32 + threadIdx.y;
    float x = t[threadIdx.x][threadIdx.y];
    __nv_bfloat16 h = __float2bfloat16_rn(x);
    g_CfTH[k_out * Ii + c_out] = h;
    g_CfTL[k_out * Ii + c_out] = __float2bfloat16_rn(x - __bfloat162float(h));
}

// ---------------- user GNN: G_u.  4 rows/block, 64 threads/row, float4/k.
__global__ void __launch_bounds__(256) user_gnn_kernel(
    const int* __restrict__ pos_cols, const float* __restrict__ pos_vals,
    const float* __restrict__ item_sv, const float* __restrict__ user_sv) {
    int tid = threadIdx.x;
    int seg = tid >> 6, lane = tid & 63;
    int r = blockIdx.x * 4 + seg;
    int s0 = g_rowstart[r], n = g_rowcnt[r];
    const float4* isv = (const float4*)item_sv;
    float4 acc = make_float4(0.f, 0.f, 0.f, 0.f);
    int j = 0;
    for (; j + 4 <= n; j += 4) {
        int c0 = __ldg(&pos_cols[s0 + j]);
        int c1 = __ldg(&pos_cols[s0 + j + 1]);
        int c2 = __ldg(&pos_cols[s0 + j + 2]);
        int c3 = __ldg(&pos_cols[s0 + j + 3]);
        float v0 = __ldg(&pos_vals[s0 + j]);
        float v1 = __ldg(&pos_vals[s0 + j + 1]);
        float v2 = __ldg(&pos_vals[s0 + j + 2]);
        float v3 = __ldg(&pos_vals[s0 + j + 3]);
        float4 a0 = isv[c0 * 64 + lane];
        float4 a1 = isv[c1 * 64 + lane];
        float4 a2 = isv[c2 * 64 + lane];
        float4 a3 = isv[c3 * 64 + lane];
        acc.x += v0 * a0.x + v1 * a1.x + v2 * a2.x + v3 * a3.x;
        acc.y += v0 * a0.y + v1 * a1.y + v2 * a2.y + v3 * a3.y;
        acc.z += v0 * a0.z + v1 * a1.z + v2 * a2.z + v3 * a3.z;
        acc.w += v0 * a0.w + v1 * a1.w + v2 * a2.w + v3 * a3.w;
    }
    for (; j < n; j++) {
        int c = __ldg(&pos_cols[s0 + j]);
        float v = __ldg(&pos_vals[s0 + j]);
        float4 a = isv[c * 64 + lane];
        acc.x += v * a.x; acc.y += v * a.y; acc.z += v * a.z; acc.w += v * a.w;
    }
    float4 us = ((const float4*)user_sv)[r * 64 + lane];
    float4 o;
    o.x = 0.5f * (acc.x * INV_COEFF + us.x);
    o.y = 0.5f * (acc.y * INV_COEFF + us.y);
    o.z = 0.5f * (acc.z * INV_COEFF + us.z);
    o.w = 0.5f * (acc.w * INV_COEFF + us.w);
    ((float4*)g_Gu)[r * 64 + lane] = o;
}

// -------- fused item GNN (/lambda folded, -> GiT hi/lo) + St hi/lo.
__global__ void __launch_bounds__(256) item_s_kernel(
    const int* __restrict__ pos_rows, const float* __restrict__ pos_vals,
    const float* __restrict__ user_sv, const float* __restrict__ item_sv,
    const float* __restrict__ lambda_mat) {
    int tid = threadIdx.x;
    int seg = tid >> 6, lane = tid & 63;
    int c = blockIdx.x * 4 + seg;
    int s0 = g_coloff[c], n = g_colcnt[c];
    const float4* usv = (const float4*)user_sv;
    const float4* guv = (const float4*)g_Gu;
    float4 accI = make_float4(0.f, 0.f, 0.f, 0.f);
    float4 accS = make_float4(0.f, 0.f, 0.f, 0.f);
    int j = 0;
    for (; j + 4 <= n; j += 4) {
        int p0 = __ldg(&g_colperm[s0 + j]);
        int p1 = __ldg(&g_colperm[s0 + j + 1]);
        int p2 = __ldg(&g_colperm[s0 + j + 2]);
        int p3 = __ldg(&g_colperm[s0 + j + 3]);
        int r0 = __ldg(&pos_rows[p0]);
        int r1 = __ldg(&pos_rows[p1]);
        int r2 = __ldg(&pos_rows[p2]);
        int r3 = __ldg(&pos_rows[p3]);
        float v0 = __ldg(&pos_vals[p0]);
        float v1 = __ldg(&pos_vals[p1]);
        float v2 = __ldg(&pos_vals[p2]);
        float v3 = __ldg(&pos_vals[p3]);
        float4 u0 = usv[r0 * 64 + lane];
        float4 u1 = usv[r1 * 64 + lane];
        float4 u2 = usv[r2 * 64 + lane];
        float4 u3 = usv[r3 * 64 + lane];
        float4 q0 = guv[r0 * 64 + lane];
        float4 q1 = guv[r1 * 64 + lane];
        float4 q2 = guv[r2 * 64 + lane];
        float4 q3 = guv[r3 * 64 + lane];
        accI.x += v0 * u0.x + v1 * u1.x + v2 * u2.x + v3 * u3.x;
        accI.y += v0 * u0.y + v1 * u1.y + v2 * u2.y + v3 * u3.y;
        accI.z += v0 * u0.z + v1 * u1.z + v2 * u2.z + v3 * u3.z;
        accI.w += v0 * u0.w + v1 * u1.w + v2 * u2.w + v3 * u3.w;
        accS.x += v0 * q0.x + v1 * q1.x + v2 * q2.x + v3 * q3.x;
        accS.y += v0 * q0.y + v1 * q1.y + v2 * q2.y + v3 * q3.y;
        accS.z += v0 * q0.z + v1 * q1.z + v2 * q2.z + v3 * q3.z;
        accS.w += v0 * q0.w + v1 * q1.w + v2 * q2.w + v3 * q3.w;
    }
    for (; j < n; j++) {
        int p = __ldg(&g_colperm[s0 + j]);
        int r = __ldg(&pos_rows[p]);
        float v = __ldg(&pos_vals[p]);
        float4 u = usv[r * 64 + lane];
        float4 q = guv[r * 64 + lane];
        accI.x += v * u.x; accI.y += v * u.y; accI.z += v * u.z; accI.w += v * u.w;
        accS.x += v * q.x; accS.y += v * q.y; accS.z += v * q.z; accS.w += v * q.w;
    }
    float4 iv = ((const float4*)item_sv)[c * 64 + lane];
    float4 lam = ((const float4*)lambda_mat)[lane];
    float gi[4], st[4];
    gi[0] = 0.5f * (accI.x * INV_COEFF + iv.x) / lam.x;
    gi[1] = 0.5f * (accI.y * INV_COEFF + iv.y) / lam.y;
    gi[2] = 0.5f * (accI.z * INV_COEFF + iv.z) / lam.z;
    gi[3] = 0.5f * (accI.w * INV_COEFF + iv.w) / lam.w;
    st[0] = accS.x; st[1] = accS.y; st[2] = accS.z; st[3] = accS.w;
#pragma unroll
    for (int i = 0; i < 4; i++) {
        int k = lane * 4 + i;
        __nv_bfloat16 h = __float2bfloat16_rn(gi[i]);
        g_GiTH[k * Ii + c] = h;
        g_GiTL[k * Ii + c] = __float2bfloat16_rn(gi[i] - __bfloat162float(h));
        __nv_bfloat16 sh = __float2bfloat16_rn(st[i]);
        g_StH[c * Kk + k] = sh;
        g_StL[c * Kk + k] = __float2bfloat16_rn(st[i] - __bfloat162float(sh));
    }
}

// ===================== mma.sync bf16-split GEMM ============================
// 512 threads (16 warps, 4x4), warp tile 32x32, BK=64, 3-stage cp.async
// pipeline, one __syncthreads per iteration. Fragment loads STREAMED per-mt
// (B up front, A per mt immediately before its MMAs) so ptxas can interleave
// LDS of mt+1 into the MMA shadow of mt within the register budget.

__device__ __forceinline__ void cp16(uint32_t dst, const void* src) {
    asm volatile("cp.async.cg.shared.global [%0], [%1], 16;"
                 :: "r"(dst), "l"(__cvta_generic_to_global(src)));
}
#define CP_COMMIT() asm volatile("cp.async.commit_group;")
#define CP_WAIT1()  asm volatile("cp.async.wait_group 1;")

__device__ __forceinline__ uint32_t smem_u32(const void* p) {
    uint32_t a;
    asm("{ .reg .u64 t; cvta.to.shared.u64 t, %1; cvt.u32.u64 %0, t; }"
        : "=r"(a) : "l"(p));
    return a;
}

#define MMA_BF16(d, a, b) \
    asm volatile("mma.sync.aligned.m16n8k16.row.col.f32.bf16.bf16.f32 " \
        "{%0,%1,%2,%3}, {%4,%5,%6,%7}, {%8,%9}, {%0,%1,%2,%3};" \
        : "+f"((d)[0]), "+f"((d)[1]), "+f"((d)[2]), "+f"((d)[3]) \
        : "r"((a)[0]), "r"((a)[1]), "r"((a)[2]), "r"((a)[3]), \
          "r"((b)[0]), "r"((b)[1]))

#define PLANE 16384            // 128 rows x 128 B
#define STAGE 65536            // 4 planes
#define GEMM_SMEM 196608       // 3 stages
#define GEMM_THREADS 512

template <int MODE>
__device__ __forceinline__ void gemm_core(
    int M, int N, int K,
    const __nv_bfloat16* __restrict__ AH, const __nv_bfloat16* __restrict__ AL,
    const __nv_bfloat16* __restrict__ BH, const __nv_bfloat16* __restrict__ BL,
    float* __restrict__ C,
    __nv_bfloat16* __restrict__ CH, __nv_bfloat16* __restrict__ CL,
    unsigned* cmin, float* csum, char* dsm)
{
    __shared__ unsigned sMin[128];
    __shared__ float sSum[128];

    int tid = threadIdx.x;
    int l = tid & 31, wid = tid >> 5;            // 16 warps
    int wm = wid >> 2, wn = wid & 3;             // 4 x 4 warps, tile 32x32
    int m0 = blockIdx.y * 128, n0 = blockIdx.x * 128;

    if (MODE == 1 && tid < 128) { sMin[tid] = 0xFFFFFFFFu; sSum[tid] = 0.0f; }

    float acc[2][4][4];
#pragma unroll
    for (int a = 0; a < 2; a++)
#pragma unroll
        for (int b = 0; b < 4; b++)
#pragma unroll
            for (int c = 0; c < 4; c++) acc[a][b][c] = 0.0f;

    uint32_t sb = smem_u32(dsm);
    int r_ld = tid >> 2;                   // row 0..127
    int cb_ld = (tid & 3) * 2;             // 2 of 8 16B-chunks per row
    int rsw = r_ld & 7;

    int NIT = K >> 6;

    auto load_stage = [&](int s, int it) {
        uint32_t stb = sb + s * STAGE;
        int k0 = it << 6;
        const __nv_bfloat16* ah = AH + (size_t)(m0 + r_ld) * K + k0;
        const __nv_bfloat16* al = AL + (size_t)(m0 + r_ld) * K + k0;
        const __nv_bfloat16* bh = BH + (size_t)(n0 + r_ld) * K + k0;
        const __nv_bfloat16* bl = BL + (size_t)(n0 + r_ld) * K + k0;
#pragma unroll
        for (int c = cb_ld; c < cb_ld + 2; c++) {
            uint32_t off = r_ld * 128 + ((c ^ rsw) & 7) * 16;
            cp16(stb + off,             ah + c * 8);
            cp16(stb + PLANE + off,     al + c * 8);
            cp16(stb + 2 * PLANE + off, bh + c * 8);
            cp16(stb + 3 * PLANE + off, bl + c * 8);
        }
    };

    load_stage(0, 0);
    CP_COMMIT();

    for (int it = 0; it < NIT; it++) {
        if (it + 1 < NIT) load_stage((it + 1) % 3, it + 1);
        CP_COMMIT();
        CP_WAIT1();
        __syncthreads();

        const char* st = dsm + (it % 3) * STAGE;
#pragma unroll
        for (int ks = 0; ks < 4; ks++) {
            // ---- B fragments for this ks (shared by both mt) ----
            uint32_t bh[4][2], bl4[4][2];
#pragma unroll
            for (int nt = 0; nt < 4; nt++) {
                int row = wn * 32 + nt * 8 + (l >> 2);
                int f = row & 7;
                int pos = (l & 3) << 2;
                uint32_t o0 = row * 128 + (((ks * 2)     ^ f) << 4) + pos;
                uint32_t o1 = row * 128 + (((ks * 2 + 1) ^ f) << 4) + pos;
                bh[nt][0] = *(const uint32_t*)(st + 2 * PLANE + o0);
                bh[nt][1] = *(const uint32_t*)(st + 2 * PLANE + o1);
                bl4[nt][0] = *(const uint32_t*)(st + 3 * PLANE + o0);
                bl4[nt][1] = *(const uint32_t*)(st + 3 * PLANE + o1);
            }
            // ---- stream A fragments per mt, MMAs immediately after ----
#pragma unroll
            for (int mt = 0; mt < 2; mt++) {
                int row = wm * 32 + mt * 16 + (l >> 2);
                int f = row & 7;             // same for row and row+8
                int pos = (l & 3) << 2;
                uint32_t o00 = row * 128 + (((ks * 2)     ^ f) << 4) + pos;
                uint32_t o01 = row * 128 + (((ks * 2 + 1) ^ f) << 4) + pos;
                uint32_t o10 = (row + 8) * 128 + (((ks * 2)     ^ f) << 4) + pos;
                uint32_t o11 = (row + 8) * 128 + (((ks * 2 + 1) ^ f) << 4) + pos;
                uint32_t ah[4], al4[4];
                ah[0] = *(const uint32_t*)(st + o00);
                ah[1] = *(const uint32_t*)(st + o10);
                ah[2] = *(const uint32_t*)(st + o01);
                ah[3] = *(const uint32_t*)(st + o11);
                al4[0] = *(const uint32_t*)(st + PLANE + o00);
                al4[1] = *(const uint32_t*)(st + PLANE + o10);
                al4[2] = *(const uint32_t*)(st + PLANE + o01);
                al4[3] = *(const uint32_t*)(st + PLANE + o11);
#pragma unroll
                for (int nt = 0; nt < 4; nt++) {
                    MMA_BF16(acc[mt][nt], ah, bh[nt]);
                    MMA_BF16(acc[mt][nt], ah, bl4[nt]);
                    MMA_BF16(acc[mt][nt], al4, bh[nt]);
                }
            }
        }
        // no bottom barrier: 3-stage distance keeps writer off live stages
    }

    __syncthreads();   // protect epilogue smem reuse ordering

    if (MODE == 0 || MODE == 2) {
#pragma unroll
        for (int mt = 0; mt < 2; mt++) {
            int row = m0 + wm * 32 + mt * 16 + (l >> 2);
#pragma unroll
            for (int nt = 0; nt < 4; nt++) {
                int col = n0 + wn * 32 + nt * 8 + ((l & 3) << 1);
                float v0 = acc[mt][nt][0], v1 = acc[mt][nt][1];
                float v2 = acc[mt][nt][2], v3 = acc[mt][nt][3];
                *(float2*)&C[(size_t)row * N + col] = make_float2(v0, v1);
                *(float2*)&C[(size_t)(row + 8) * N + col] = make_float2(v2, v3);
                if (MODE == 2) {
                    __nv_bfloat16 h0 = __float2bfloat16_rn(v0);
                    __nv_bfloat16 h1 = __float2bfloat16_rn(v1);
                    __nv_bfloat16 h2 = __float2bfloat16_rn(v2);
                    __nv_bfloat16 h3 = __float2bfloat16_rn(v3);
                    *(__nv_bfloat162*)&CH[(size_t)row * N + col] = __halves2bfloat162(h0, h1);
                    *(__nv_bfloat162*)&CH[(size_t)(row + 8) * N + col] = __halves2bfloat162(h2, h3);
                    *(__nv_bfloat162*)&CL[(size_t)row * N + col] =
                        __halves2bfloat162(__float2bfloat16_rn(v0 - __bfloat162float(h0)),
                                           __float2bfloat16_rn(v1 - __bfloat162float(h1)));
                    *(__nv_bfloat162*)&CL[(size_t)(row + 8) * N + col] =
                        __halves2bfloat162(__float2bfloat16_rn(v2 - __bfloat162float(h2)),
                                           __float2bfloat16_rn(v3 - __bfloat162float(h3)));
                }
            }
        }
    } else {   // MODE 1: fused column min/sum
#pragma unroll
        for (int nt = 0; nt < 4; nt++) {
            float mn0 = acc[0][nt][0], sm0 = 0.0f;
            float mn1 = acc[0][nt][1], sm1 = 0.0f;
#pragma unroll
            for (int mt = 0; mt < 2; mt++) {
                mn0 = fminf(mn0, fminf(acc[mt][nt][0], acc[mt][nt][2]));
                sm0 += acc[mt][nt][0] + acc[mt][nt][2];
                mn1 = fminf(mn1, fminf(acc[mt][nt][1], acc[mt][nt][3]));
                sm1 += acc[mt][nt][1] + acc[mt][nt][3];
            }
#pragma unroll
            for (int d = 4; d < 32; d <<= 1) {
                sm0 += __shfl_xor_sync(0xFFFFFFFFu, sm0, d);
                sm1 += __shfl_xor_sync(0xFFFFFFFFu, sm1, d);
                mn0 = fminf(mn0, __shfl_xor_sync(0xFFFFFFFFu, mn0, d));
                mn1 = fminf(mn1, __shfl_xor_sync(0xFFFFFFFFu, mn1, d));
            }
            if ((l >> 2) == 0) {
                int c = wn * 32 + nt * 8 + ((l & 3) << 1);
                atomicMin(&sMin[c], fenc(mn0));
                atomicAdd(&sSum[c], sm0);
                atomicMin(&sMin[c + 1], fenc(mn1));
                atomicAdd(&sSum[c + 1], sm1);
            }
        }
        __syncthreads();
        if (tid < 128) {
            atomicMin(&cmin[n0 + tid], sMin[tid]);
            atomicAdd(&csum[n0 + tid], sSum[tid]);
        }
    }
}

// wrappers
__global__ void __launch_bounds__(GEMM_THREADS, 1) gemm_e_kernel(
    const __nv_bfloat16* AH, const __nv_bfloat16* AL,
    const __nv_bfloat16* BH, const __nv_bfloat16* BL,
    float* C, __nv_bfloat16* CH, __nv_bfloat16* CL) {
    extern __shared__ char dsm[];
    gemm_core<2>(Uu, Kk, Ii, AH, AL, BH, BL, C, CH, CL, nullptr, nullptr, dsm);
}

__global__ void __launch_bounds__(GEMM_THREADS, 1) gemm_stats_kernel(
    const __nv_bfloat16* AH, const __nv_bfloat16* AL,
    const __nv_bfloat16* BH, const __nv_bfloat16* BL,
    unsigned* cmin, float* csum) {
    extern __shared__ char dsm[];
    gemm_core<1>(Uu, Ii, Kk, AH, AL, BH, BL,
                 nullptr, nullptr, nullptr, cmin, csum, dsm);
}

__global__ void __launch_bounds__(GEMM_THREADS, 1) gemm_out_kernel(
    const __nv_bfloat16* AH, const __nv_bfloat16* AL,
    const __nv_bfloat16* BH, const __nv_bfloat16* BL,
    float* C) {
    extern __shared__ char dsm[];
    gemm_core<0>(Uu, Ii, Kk, AH, AL, BH, BL,
                 C, nullptr, nullptr, nullptr, nullptr, dsm);
}

// ------------------- per-row mat_expo entries -> p1/p2 (compute_P fusion)
__global__ void entry_kernel(const int* __restrict__ pos_cols,
                             const float* __restrict__ pos_vals,
                             const float* __restrict__ usf) {
    int r = blockIdx.x, t = threadIdx.x;
    int mk = g_minkey[r];
    if (mk == 0x7FFFFFFF) { if (t == 0) g_has[r] = 0; return; }
    int eidx = mk % NNZ;
    int c1 = pos_cols[eidx];
    float v1 = pos_vals[eidx];
    int c2 = (c1 + 1) & (Ii - 1);
    float a = g_E1[r * Kk + t];
    float e1 = a * usf[c1 * Kk + t];
    float e2 = a * usf[c2 * Kk + t];
    __shared__ float s1[256], s2[256];
    s1[t] = e1; s2[t] = e2;
    __syncthreads();
    for (int off = 128; off > 0; off >>= 1) {
        if (t < off) { s1[t] += s1[t + off]; s2[t] += s2[t + off]; }
        __syncthreads();
    }
    if (t == 0) {
        float E1v = s1[0], E2v = s2[0];
        float m1 = fdec(g_colmin[c1]), m2 = fdec(g_colmin[c2]);
        float sum1 = g_colsum[c1] - (float)Uu * m1 + (float)Uu * 1e-8f;
        float sum2 = g_colsum[c2] - (float)Uu * m2 + (float)Uu * 1e-8f;
        float n1 = (E1v - m1 + 1e-8f) / sum1;
        float n2 = (E2v - m2 + 1e-8f) / sum2;
        float d1 = (v1 == 0.0f) ? 1e-5f : v1;
        float d2 = (v1 == 0.0f) ? 1e-5f : -v1;
        g_p1[r] = n1 / d1;
        g_p2[r] = n2 / d2;
        g_c1[r] = c1;
        g_c2[r] = c2;
        g_has[r] = 1;
    }
}

// ------------------------------------------- out += 0.2 * mat_adjust
__global__ void adjust_kernel(float* __restrict__ out) {
    int r = blockIdx.x * blockDim.x + threadIdx.x;
    if (r >= Uu || !g_has[r]) return;
    out[(size_t)r * Ii + g_c1[r]] += 0.2f * g_p1[r];
    out[(size_t)r * Ii + g_c2[r]] += 0.2f * g_p2[r];
}

extern "C" void kernel_launch(void* const* d_in, const int* in_sizes, int n_in,
                              void* d_out, int out_size) {
    const float* adj       = (const float*)d_in[0];
    const float* norm_adj  = (const float*)d_in[1];
    const float* user_sv   = (const float*)d_in[2];
    const float* item_sv   = (const float*)d_in[3];
    const float* user_sv_f = (const float*)d_in[4];
    const float* item_sv_f = (const float*)d_in[5];
    const int*   pos_rows  = (const int*)d_in[6];
    const int*   pos_cols  = (const int*)d_in[7];
    const float* pos_vals  = (const float*)d_in[8];
    const float* lambda_m  = (const float*)d_in[9];
    const float* lambda_p  = (const float*)d_in[10];
    float* out = (float*)d_out;

    void *adjH, *adjL, *nrmH, *nrmL, *cfH, *cfL, *giH, *giL;
    void *usH, *usL, *stH, *stL, *e1H, *e1L, *e2H, *e2L, *e1f, *e2f;
    void *cminp, *csump;
    cudaGetSymbolAddress(&adjH, g_adjH); cudaGetSymbolAddress(&adjL, g_adjL);
    cudaGetSymbolAddress(&nrmH, g_nrmH); cudaGetSymbolAddress(&nrmL, g_nrmL);
    cudaGetSymbolAddress(&cfH, g_CfTH);  cudaGetSymbolAddress(&cfL, g_CfTL);
    cudaGetSymbolAddress(&giH, g_GiTH);  cudaGetSymbolAddress(&giL, g_GiTL);
    cudaGetSymbolAddress(&usH, g_usfH);  cudaGetSymbolAddress(&usL, g_usfL);
    cudaGetSymbolAddress(&stH, g_StH);   cudaGetSymbolAddress(&stL, g_StL);
    cudaGetSymbolAddress(&e1H, g_E1H);   cudaGetSymbolAddress(&e1L, g_E1L);
    cudaGetSymbolAddress(&e2H, g_E2H);   cudaGetSymbolAddress(&e2L, g_E2L);
    cudaGetSymbolAddress(&e1f, g_E1);    cudaGetSymbolAddress(&e2f, g_E2);
    cudaGetSymbolAddress(&cminp, g_colmin); cudaGetSymbolAddress(&csump, g_colsum);

    cudaFuncSetAttribute(gemm_e_kernel, cudaFuncAttributeMaxDynamicSharedMemorySize, GEMM_SMEM);
    cudaFuncSetAttribute(gemm_stats_kernel, cudaFuncAttributeMaxDynamicSharedMemorySize, GEMM_SMEM);
    cudaFuncSetAttribute(gemm_out_kernel, cudaFuncAttributeMaxDynamicSharedMemorySize, GEMM_SMEM);

    // one-time stream/event creation (host resources, not device memory)
    static cudaStream_t s2 = nullptr, s3 = nullptr;
    static cudaEvent_t evFork, evBuild, evNrm, evUsf, evEntry;
    if (s2 == nullptr) {
        cudaStreamCreateWithFlags(&s2, cudaStreamNonBlocking);
        cudaStreamCreateWithFlags(&s3, cudaStreamNonBlocking);
        cudaEventCreateWithFlags(&evFork,  cudaEventDisableTiming);
        cudaEventCreateWithFlags(&evBuild, cudaEventDisableTiming);
        cudaEventCreateWithFlags(&evNrm,   cudaEventDisableTiming);
        cudaEventCreateWithFlags(&evUsf,   cudaEventDisableTiming);
        cudaEventCreateWithFlags(&evEntry, cudaEventDisableTiming);
    }

    // ---- main: init, then fork
    init_kernel<<<Uu / 256, 256>>>();
    cudaEventRecord(evFork, 0);
    cudaStreamWaitEvent(s2, evFork, 0);
    cudaStreamWaitEvent(s3, evFork, 0);

    // ---- s2: adj planes -> CfT planes -> GEMM1 (E1 + planes)
    split_kernel<<<(Uu * Ii / 4 + 255) / 256, 256, 0, s2>>>(
        (const float4*)adj, (__nv_bfloat162*)adjH, (__nv_bfloat162*)adjL, Uu * Ii / 4);
    cft_kernel<<<dim3(Ii / 32, Kk / 32), dim3(32, 32), 0, s2>>>(item_sv_f, lambda_p);
    gemm_e_kernel<<<dim3(Kk / 128, Uu / 128), GEMM_THREADS, GEMM_SMEM, s2>>>(
        (const __nv_bfloat16*)adjH, (const __nv_bfloat16*)adjL,
        (const __nv_bfloat16*)cfH,  (const __nv_bfloat16*)cfL,
        (float*)e1f, (__nv_bfloat16*)e1H, (__nv_bfloat16*)e1L);

    // ---- s3: norm planes, usf planes
    split_kernel<<<(Uu * Ii / 4 + 255) / 256, 256, 0, s3>>>(
        (const float4*)norm_adj, (__nv_bfloat162*)nrmH, (__nv_bfloat162*)nrmL, Uu * Ii / 4);
    cudaEventRecord(evNrm, s3);
    split_kernel<<<(Ii * Kk / 4 + 255) / 256, 256, 0, s3>>>(
        (const float4*)user_sv_f, (__nv_bfloat162*)usH, (__nv_bfloat162*)usL, Ii * Kk / 4);
    cudaEventRecord(evUsf, s3);

    // ---- main: sparse metadata + GNN chain
    build_kernel<<<(NNZ + 255) / 256, 256>>>(pos_rows, pos_cols);
    cudaEventRecord(evBuild, 0);
    col_scan_kernel<<<1, 256>>>();
    scatter_kernel<<<(NNZ + 255) / 256, 256>>>(pos_cols);
    user_gnn_kernel<<<Uu / 4, 256>>>(pos_cols, pos_vals, item_sv, user_sv);
    item_s_kernel<<<Ii / 4, 256>>>(pos_rows, pos_vals, user_sv, item_sv, lambda_m);

    // ---- s2: stats GEMM (needs E1 planes + usf planes), then entry
    cudaStreamWaitEvent(s2, evUsf, 0);
    gemm_stats_kernel<<<dim3(Ii / 128, Uu / 128), GEMM_THREADS, GEMM_SMEM, s2>>>(
        (const __nv_bfloat16*)e1H, (const __nv_bfloat16*)e1L,
        (const __nv_bfloat16*)usH, (const __nv_bfloat16*)usL,
        (unsigned*)cminp, (float*)csump);
    cudaStreamWaitEvent(s2, evBuild, 0);
    entry_kernel<<<Uu, 256, 0, s2>>>(pos_cols, pos_vals, user_sv_f);
    cudaEventRecord(evEntry, s2);

    // ---- main: GEMM2 (needs nrm planes + GiT from item_s), out GEMM, adjust
    cudaStreamWaitEvent(0, evNrm, 0);
    gemm_e_kernel<<<dim3(Kk / 128, Uu / 128), GEMM_THREADS, GEMM_SMEM>>>(
        (const __nv_bfloat16*)nrmH, (const __nv_bfloat16*)nrmL,
        (const __nv_bfloat16*)giH,  (const __nv_bfloat16*)giL,
        (float*)e2f, (__nv_bfloat16*)e2H, (__nv_bfloat16*)e2L);
    gemm_out_kernel<<<dim3(Ii / 128, Uu / 128), GEMM_THREADS, GEMM_SMEM>>>(
        (const __nv_bfloat16*)e2H, (const __nv_bfloat16*)e2L,
        (const __nv_bfloat16*)stH, (const __nv_bfloat16*)stL, out);
    cudaStreamWaitEvent(0, evEntry, 0);
    adjust_kernel<<<Uu / 256, 256>>>(out);
}